// round 13
// baseline (speedup 1.0000x reference)
#include <cuda_runtime.h>

// out[i,j] = hA[i] + hB[j] + 1 - 0.5 * sum_d s*lg2(s),  s = a + b (raw sum),
// using sum_d m*lg2(m) = 0.5*sum_d s*lg2(s) - 1 (rows normalized).
// Fused: blocks 0..63 produce row entropies (wave-1) -> g_done; 8192 tile
// blocks accumulate via RED.ADD.F32; bz==7 (last-scheduled) folds constants.
// NEW: 1 of 8 logs per d-body computed by a scalar FMA-pipe polynomial
// (rotating across bodies) to shave the MUFU.LG2 pipe floor by 1/8.

static constexpr int Dc = 512;
static constexpr int TM = 32;
static constexpr int TN = 32;
static constexpr int KB = 64;
static constexpr int LDA = 36;
static constexpr int SPLIT = 8;
static constexpr int DPART = Dc / SPLIT; // 64
static constexpr int EBLK = 64;

__device__ float g_hA[1024];
__device__ float g_hB[1024];
__device__ int   g_done;   // monotonic across graph replays

// scalar log2 via deg-6 Taylor around 3/2: s = 2^e * f, f in [1,2),
// w = (2/3)f - 1 in [-1/3,1/3), lg2(s) = e + lg2(3/2) + w*P(w).
__device__ __forceinline__ float lg2_poly(float s) {
    unsigned u = __float_as_uint(s);
    float f = __uint_as_float((u & 0x7FFFFFu) | 0x3F800000u);
    float e = __uint_as_float((u >> 23) + 0x4B000000u) - 8388735.0f; // E-127 exact
    float w = __fmaf_rn(f, 0.66666667f, -1.0f);
    float p = -0.24044917f;                    // -1/(6 ln2)
    p = __fmaf_rn(p, w, 0.28853901f);          //  1/(5 ln2)
    p = __fmaf_rn(p, w, -0.36067376f);         // -1/(4 ln2)
    p = __fmaf_rn(p, w, 0.48089835f);          //  1/(3 ln2)
    p = __fmaf_rn(p, w, -0.72134752f);         // -1/(2 ln2)
    p = __fmaf_rn(p, w, 1.44269504f);          //  1/ln2
    return __fmaf_rn(w, p, e + 0.58496250f);   // e + lg2(3/2) + w*P
}

__global__ __launch_bounds__(128, 8)
void jsd_fused(const float* __restrict__ A, const float* __restrict__ B,
               float* __restrict__ out, int M) {
    const int bid = blockIdx.x;
    const int tid = threadIdx.x;

    if (bid < EBLK) {
        // ---- row-entropy producer: 32 rows/block, 8 rows/warp -------------
        const int warp = tid >> 5;
        const int lane = tid & 31;
        #pragma unroll 1
        for (int k = 0; k < 8; ++k) {
            const int row = bid * 32 + warp * 8 + k;
            const bool isA = row < 1024;
            const int r = isA ? row : row - 1024;
            const float4* p = reinterpret_cast<const float4*>(
                (isA ? A : B) + (size_t)r * Dc);
            float4 v0 = p[lane];
            float4 v1 = p[lane + 32];
            float4 v2 = p[lane + 64];
            float4 v3 = p[lane + 96];
            float s = 0.5f * v0.x * __log2f(v0.x) + 0.5f * v0.y * __log2f(v0.y)
                    + 0.5f * v0.z * __log2f(v0.z) + 0.5f * v0.w * __log2f(v0.w)
                    + 0.5f * v1.x * __log2f(v1.x) + 0.5f * v1.y * __log2f(v1.y)
                    + 0.5f * v1.z * __log2f(v1.z) + 0.5f * v1.w * __log2f(v1.w)
                    + 0.5f * v2.x * __log2f(v2.x) + 0.5f * v2.y * __log2f(v2.y)
                    + 0.5f * v2.z * __log2f(v2.z) + 0.5f * v2.w * __log2f(v2.w)
                    + 0.5f * v3.x * __log2f(v3.x) + 0.5f * v3.y * __log2f(v3.y)
                    + 0.5f * v3.z * __log2f(v3.z) + 0.5f * v3.w * __log2f(v3.w);
            #pragma unroll
            for (int off = 16; off > 0; off >>= 1)
                s += __shfl_xor_sync(0xFFFFFFFFu, s, off);
            if (lane == 0) {
                if (isA) g_hA[r] = s; else g_hB[r] = s;
            }
        }
        __syncthreads();
        if (tid == 0) {
            __threadfence();
            atomicAdd(&g_done, 1);
        }
        return;
    }

    // ---- tile block: one 64-wide D-slice of one 32x32 output tile --------
    __shared__ float As[KB][LDA];
    __shared__ float Bs[KB][LDA];

    const int tb = bid - EBLK;
    const int bx = tb & 31;
    const int by = (tb >> 5) & 31;
    const int bz = tb >> 10;               // 0..7; bz==7 scheduled last
    const int i0 = by * TM;
    const int j0 = bx * TN;
    const int d0 = bz * DPART;

    const int sd = tid & 63;
    const int sw = tid >> 6;
    const float* pA = A + (size_t)(i0 + sw) * Dc + d0 + sd;
    const float* pB = B + (size_t)(j0 + sw) * Dc + d0 + sd;
    float* stA = &As[sd][sw];
    float* stB = &Bs[sd][sw];

    #pragma unroll
    for (int e = 0; e < 16; ++e) {
        stA[e * 2] = pA[e * 2 * Dc];
        stB[e * 2] = pB[e * 2 * Dc];
    }
    __syncthreads();

    const int tx = tid & 7;
    const int ty = tid >> 3;

    float acc[8] = {0.f, 0.f, 0.f, 0.f, 0.f, 0.f, 0.f, 0.f};
    // element index mapping: idx = u*4 + v, u in {0,1}, v in {0..3}

    #pragma unroll 1
    for (int d8 = 0; d8 < KB / 8; ++d8) {
        #pragma unroll
        for (int dd = 0; dd < 8; ++dd) {
            const int d = d8 * 8 + dd;
            float2 a2 = *reinterpret_cast<const float2*>(&As[d][ty * 2]);
            float4 b4 = *reinterpret_cast<const float4*>(&Bs[d][tx * 4]);
            float sv[8];
            sv[0] = a2.x + b4.x; sv[1] = a2.x + b4.y;
            sv[2] = a2.x + b4.z; sv[3] = a2.x + b4.w;
            sv[4] = a2.y + b4.x; sv[5] = a2.y + b4.y;
            sv[6] = a2.y + b4.z; sv[7] = a2.y + b4.w;
            #pragma unroll
            for (int k = 0; k < 8; ++k) {
                // rotate the polynomial-routed element across the 8 bodies
                float lg = (k == dd) ? lg2_poly(sv[k]) : __log2f(sv[k]);
                acc[k] = __fmaf_rn(sv[k], lg, acc[k]);
            }
        }
    }

    #pragma unroll
    for (int k = 0; k < 8; ++k) acc[k] *= -0.5f;

    if (bz == SPLIT - 1) {
        if (tid == 0) {
            while (atomicAdd(&g_done, 0) < EBLK) __nanosleep(64);
        }
        __syncthreads();
        float ha0 = __ldcg(&g_hA[i0 + ty * 2]) + 1.0f;
        float ha1 = __ldcg(&g_hA[i0 + ty * 2 + 1]) + 1.0f;
        float hb0 = __ldcg(&g_hB[j0 + tx * 4]);
        float hb1 = __ldcg(&g_hB[j0 + tx * 4 + 1]);
        float hb2 = __ldcg(&g_hB[j0 + tx * 4 + 2]);
        float hb3 = __ldcg(&g_hB[j0 + tx * 4 + 3]);
        acc[0] += ha0 + hb0; acc[1] += ha0 + hb1;
        acc[2] += ha0 + hb2; acc[3] += ha0 + hb3;
        acc[4] += ha1 + hb0; acc[5] += ha1 + hb1;
        acc[6] += ha1 + hb2; acc[7] += ha1 + hb3;
    }

    float* o0 = &out[(size_t)(i0 + ty * 2) * M + (j0 + tx * 4)];
    atomicAdd(o0 + 0, acc[0]);
    atomicAdd(o0 + 1, acc[1]);
    atomicAdd(o0 + 2, acc[2]);
    atomicAdd(o0 + 3, acc[3]);
    float* o1 = o0 + M;
    atomicAdd(o1 + 0, acc[4]);
    atomicAdd(o1 + 1, acc[5]);
    atomicAdd(o1 + 2, acc[6]);
    atomicAdd(o1 + 3, acc[7]);
}

extern "C" void kernel_launch(void* const* d_in, const int* in_sizes, int n_in,
                              void* d_out, int out_size) {
    const float* A = (const float*)d_in[0];
    const float* B = (const float*)d_in[1];
    float* out = (float*)d_out;
    const int M = in_sizes[1] / Dc;   // 1024

    cudaMemsetAsync(d_out, 0, (size_t)out_size * sizeof(float), 0);

    const int nblocks = EBLK + (M / TN) * ((in_sizes[0] / Dc) / TM) * SPLIT;
    jsd_fused<<<nblocks, 128>>>(A, B, out, M);
}

// round 14
// speedup vs baseline: 1.0185x; 1.0185x over previous
#include <cuda_runtime.h>

// out[i,j] = hA[i] + hB[j] + 1 - 0.5 * sum_d s*lg2(s),  s = a + b (raw sum),
// using sum_d m*lg2(m) = 0.5*sum_d s*lg2(s) - 1 (rows normalized).
// Fused: blocks 0..63 produce row entropies (wave-1) -> g_done; 4096 tile
// blocks (32x64 tiles, split-D=8) accumulate -0.5*s*lg2(s) via RED.ADD.F32
// onto a zeroed output; bz==7 (last-scheduled) folds hA+hB+1.
// 2x8 micro-tile: 3 LDS serve 16 elements -> minimal non-MUFU issue load.

static constexpr int Dc = 512;
static constexpr int TM = 32;            // A rows per tile
static constexpr int TN = 64;            // B rows per tile
static constexpr int KB = 64;            // == DPART: one chunk per block
static constexpr int LDA = 36;           // A smem row pad (floats)
static constexpr int LDB = 68;           // B smem row pad (floats)
static constexpr int SPLIT = 8;
static constexpr int DPART = Dc / SPLIT; // 64
static constexpr int EBLK = 64;

__device__ float g_hA[1024];
__device__ float g_hB[1024];
__device__ int   g_done;   // monotonic across graph replays

__global__ __launch_bounds__(128, 8)
void jsd_fused(const float* __restrict__ A, const float* __restrict__ B,
               float* __restrict__ out, int M) {
    const int bid = blockIdx.x;
    const int tid = threadIdx.x;

    if (bid < EBLK) {
        // ---- row-entropy producer: 32 rows/block, 8 rows/warp -------------
        const int warp = tid >> 5;
        const int lane = tid & 31;
        #pragma unroll 1
        for (int k = 0; k < 8; ++k) {
            const int row = bid * 32 + warp * 8 + k;
            const bool isA = row < 1024;
            const int r = isA ? row : row - 1024;
            const float4* p = reinterpret_cast<const float4*>(
                (isA ? A : B) + (size_t)r * Dc);
            float4 v0 = p[lane];
            float4 v1 = p[lane + 32];
            float4 v2 = p[lane + 64];
            float4 v3 = p[lane + 96];
            float s = 0.5f * v0.x * __log2f(v0.x) + 0.5f * v0.y * __log2f(v0.y)
                    + 0.5f * v0.z * __log2f(v0.z) + 0.5f * v0.w * __log2f(v0.w)
                    + 0.5f * v1.x * __log2f(v1.x) + 0.5f * v1.y * __log2f(v1.y)
                    + 0.5f * v1.z * __log2f(v1.z) + 0.5f * v1.w * __log2f(v1.w)
                    + 0.5f * v2.x * __log2f(v2.x) + 0.5f * v2.y * __log2f(v2.y)
                    + 0.5f * v2.z * __log2f(v2.z) + 0.5f * v2.w * __log2f(v2.w)
                    + 0.5f * v3.x * __log2f(v3.x) + 0.5f * v3.y * __log2f(v3.y)
                    + 0.5f * v3.z * __log2f(v3.z) + 0.5f * v3.w * __log2f(v3.w);
            #pragma unroll
            for (int off = 16; off > 0; off >>= 1)
                s += __shfl_xor_sync(0xFFFFFFFFu, s, off);
            if (lane == 0) {
                if (isA) g_hA[r] = s; else g_hB[r] = s;
            }
        }
        __syncthreads();
        if (tid == 0) {
            __threadfence();
            atomicAdd(&g_done, 1);
        }
        return;
    }

    // ---- tile block: one 64-wide D-slice of one 32x64 output tile --------
    __shared__ float As[KB][LDA];
    __shared__ float Bs[KB][LDB];

    const int tb = bid - EBLK;
    const int bx = tb & 15;                // 16 tiles across M (TN=64)
    const int by = (tb >> 4) & 31;         // 32 tiles across N (TM=32)
    const int bz = tb >> 9;                // 0..7; bz==7 scheduled last
    const int i0 = by * TM;
    const int j0 = bx * TN;
    const int d0 = bz * DPART;

    // staging: d = tid&63 (fixed), row = e*2 + (tid>>6)
    const int sd = tid & 63;
    const int sw = tid >> 6;
    const float* pA = A + (size_t)(i0 + sw) * Dc + d0 + sd;
    const float* pB = B + (size_t)(j0 + sw) * Dc + d0 + sd;
    float* stA = &As[sd][sw];
    float* stB = &Bs[sd][sw];

    #pragma unroll
    for (int e = 0; e < 16; ++e)            // A: 32 rows
        stA[e * 2] = pA[e * 2 * Dc];
    #pragma unroll
    for (int e = 0; e < 32; ++e)            // B: 64 rows
        stB[e * 2] = pB[e * 2 * Dc];
    __syncthreads();

    const int tx = tid & 7;                 // 8 col-groups of 8
    const int ty = tid >> 3;                // 16 row-groups of 2

    float acc[2][8];
    #pragma unroll
    for (int u = 0; u < 2; ++u)
        #pragma unroll
        for (int v = 0; v < 8; ++v) acc[u][v] = 0.0f;

    #pragma unroll 4
    for (int d = 0; d < KB; ++d) {
        float2 a2 = *reinterpret_cast<const float2*>(&As[d][ty * 2]);
        float4 bLo = *reinterpret_cast<const float4*>(&Bs[d][tx * 8]);
        float4 bHi = *reinterpret_cast<const float4*>(&Bs[d][tx * 8 + 4]);
        float bv[8] = {bLo.x, bLo.y, bLo.z, bLo.w, bHi.x, bHi.y, bHi.z, bHi.w};
        float s;
        #pragma unroll
        for (int v = 0; v < 8; ++v) {
            s = a2.x + bv[v]; acc[0][v] = __fmaf_rn(s, __log2f(s), acc[0][v]);
            s = a2.y + bv[v]; acc[1][v] = __fmaf_rn(s, __log2f(s), acc[1][v]);
        }
    }

    #pragma unroll
    for (int u = 0; u < 2; ++u)
        #pragma unroll
        for (int v = 0; v < 8; ++v) acc[u][v] *= -0.5f;

    if (bz == SPLIT - 1) {
        // last-scheduled group folds the per-row constants; g_done >= EBLK
        // long before these blocks run, so the spin never iterates.
        if (tid == 0) {
            while (atomicAdd(&g_done, 0) < EBLK) __nanosleep(64);
        }
        __syncthreads();
        float ha0 = __ldcg(&g_hA[i0 + ty * 2]) + 1.0f;
        float ha1 = __ldcg(&g_hA[i0 + ty * 2 + 1]) + 1.0f;
        #pragma unroll
        for (int v = 0; v < 8; ++v) {
            float hb = __ldcg(&g_hB[j0 + tx * 8 + v]);
            acc[0][v] += ha0 + hb;
            acc[1][v] += ha1 + hb;
        }
    }

    // epilogue: RED.ADD.F32, spread addresses
    float* o0 = &out[(size_t)(i0 + ty * 2) * M + (j0 + tx * 8)];
    float* o1 = o0 + M;
    #pragma unroll
    for (int v = 0; v < 8; ++v) atomicAdd(o0 + v, acc[0][v]);
    #pragma unroll
    for (int v = 0; v < 8; ++v) atomicAdd(o1 + v, acc[1][v]);
}

extern "C" void kernel_launch(void* const* d_in, const int* in_sizes, int n_in,
                              void* d_out, int out_size) {
    const float* A = (const float*)d_in[0];
    const float* B = (const float*)d_in[1];
    float* out = (float*)d_out;
    const int N = in_sizes[0] / Dc;   // 1024
    const int M = in_sizes[1] / Dc;   // 1024

    cudaMemsetAsync(d_out, 0, (size_t)out_size * sizeof(float), 0);

    const int nblocks = EBLK + (M / TN) * (N / TM) * SPLIT;  // 64 + 4096
    jsd_fused<<<nblocks, 128>>>(A, B, out, M);
}

// round 15
// speedup vs baseline: 1.0894x; 1.0696x over previous
#include <cuda_runtime.h>

// out[i,j] = hA[i] + hB[j] + 1 - 0.5 * sum_d s*lg2(s),  s = a + b (raw sum),
// using sum_d m*lg2(m) = 0.5*sum_d s*lg2(s) - 1 (rows normalized).
// Fused: blocks 0..63 produce row entropies (wave-1) -> g_done; 8192 tile
// blocks (32x32 tiles, split-D=8, 2x4 micro-tile) accumulate -0.5*s*lg2(s)
// via RED.ADD.F32 onto a zeroed output; bz==7 (last-scheduled) folds hA+hB+1.
// A tile stored transposed (AsT[row][d]) so one LDS.128 feeds 4 d-bodies.

static constexpr int Dc = 512;
static constexpr int TM = 32;
static constexpr int TN = 32;
static constexpr int KB = 64;            // == DPART: one chunk per block
static constexpr int LDT = KB + 4;       // AsT row stride (floats) = 68
static constexpr int LDA = 36;           // Bs row pad (floats)
static constexpr int SPLIT = 8;
static constexpr int DPART = Dc / SPLIT; // 64
static constexpr int EBLK = 64;

__device__ float g_hA[1024];
__device__ float g_hB[1024];
__device__ int   g_done;   // monotonic across graph replays

__global__ __launch_bounds__(128, 8)
void jsd_fused(const float* __restrict__ A, const float* __restrict__ B,
               float* __restrict__ out, int M) {
    const int bid = blockIdx.x;
    const int tid = threadIdx.x;

    if (bid < EBLK) {
        // ---- row-entropy producer: 32 rows/block, 8 rows/warp -------------
        const int warp = tid >> 5;
        const int lane = tid & 31;
        #pragma unroll 1
        for (int k = 0; k < 8; ++k) {
            const int row = bid * 32 + warp * 8 + k;
            const bool isA = row < 1024;
            const int r = isA ? row : row - 1024;
            const float4* p = reinterpret_cast<const float4*>(
                (isA ? A : B) + (size_t)r * Dc);
            float4 v0 = p[lane];
            float4 v1 = p[lane + 32];
            float4 v2 = p[lane + 64];
            float4 v3 = p[lane + 96];
            float s = 0.5f * v0.x * __log2f(v0.x) + 0.5f * v0.y * __log2f(v0.y)
                    + 0.5f * v0.z * __log2f(v0.z) + 0.5f * v0.w * __log2f(v0.w)
                    + 0.5f * v1.x * __log2f(v1.x) + 0.5f * v1.y * __log2f(v1.y)
                    + 0.5f * v1.z * __log2f(v1.z) + 0.5f * v1.w * __log2f(v1.w)
                    + 0.5f * v2.x * __log2f(v2.x) + 0.5f * v2.y * __log2f(v2.y)
                    + 0.5f * v2.z * __log2f(v2.z) + 0.5f * v2.w * __log2f(v2.w)
                    + 0.5f * v3.x * __log2f(v3.x) + 0.5f * v3.y * __log2f(v3.y)
                    + 0.5f * v3.z * __log2f(v3.z) + 0.5f * v3.w * __log2f(v3.w);
            #pragma unroll
            for (int off = 16; off > 0; off >>= 1)
                s += __shfl_xor_sync(0xFFFFFFFFu, s, off);
            if (lane == 0) {
                if (isA) g_hA[r] = s; else g_hB[r] = s;
            }
        }
        __syncthreads();
        if (tid == 0) {
            __threadfence();
            atomicAdd(&g_done, 1);
        }
        return;
    }

    // ---- tile block: one 64-wide D-slice of one 32x32 output tile --------
    __shared__ float AsT[TM][LDT];   // AsT[r][d] = a[i0+r][d0+d]  (transposed)
    __shared__ float Bs[KB][LDA];    // Bs[d][r]  = b[j0+r][d0+d]

    const int tb = bid - EBLK;
    const int bx = tb & 31;
    const int by = (tb >> 5) & 31;
    const int bz = tb >> 10;               // 0..7; bz==7 scheduled last
    const int i0 = by * TM;
    const int j0 = bx * TN;
    const int d0 = bz * DPART;

    // staging: d = tid&63 (fixed), row = e*2 + (tid>>6)
    const int sd = tid & 63;
    const int sw = tid >> 6;
    const float* pA = A + (size_t)(i0 + sw) * Dc + d0 + sd;
    const float* pB = B + (size_t)(j0 + sw) * Dc + d0 + sd;
    float* stA = &AsT[sw][sd];             // advance by 2 rows per e
    float* stB = &Bs[sd][sw];

    #pragma unroll
    for (int e = 0; e < 16; ++e) {
        stA[e * 2 * LDT] = pA[e * 2 * Dc]; // coalesced within a row
        stB[e * 2]       = pB[e * 2 * Dc];
    }
    __syncthreads();

    const int tx = tid & 7;                // 8 col-groups of 4
    const int ty = tid >> 3;               // 16 row-groups of 2

    float acc00 = 0.f, acc01 = 0.f, acc02 = 0.f, acc03 = 0.f;
    float acc10 = 0.f, acc11 = 0.f, acc12 = 0.f, acc13 = 0.f;

    const float4* aRow0 = reinterpret_cast<const float4*>(&AsT[ty * 2][0]);
    const float4* aRow1 = reinterpret_cast<const float4*>(&AsT[ty * 2 + 1][0]);

    #pragma unroll 4
    for (int d4 = 0; d4 < KB / 4; ++d4) {
        float4 a0 = aRow0[d4];             // a[row0][4d..4d+3], 1 LDS.128
        float4 a1 = aRow1[d4];             // a[row1][4d..4d+3], 1 LDS.128
        float a0v[4] = {a0.x, a0.y, a0.z, a0.w};
        float a1v[4] = {a1.x, a1.y, a1.z, a1.w};
        #pragma unroll
        for (int dd = 0; dd < 4; ++dd) {
            float4 b4 = *reinterpret_cast<const float4*>(&Bs[d4 * 4 + dd][tx * 4]);
            float s;
            s = a0v[dd] + b4.x; acc00 = __fmaf_rn(s, __log2f(s), acc00);
            s = a0v[dd] + b4.y; acc01 = __fmaf_rn(s, __log2f(s), acc01);
            s = a0v[dd] + b4.z; acc02 = __fmaf_rn(s, __log2f(s), acc02);
            s = a0v[dd] + b4.w; acc03 = __fmaf_rn(s, __log2f(s), acc03);
            s = a1v[dd] + b4.x; acc10 = __fmaf_rn(s, __log2f(s), acc10);
            s = a1v[dd] + b4.y; acc11 = __fmaf_rn(s, __log2f(s), acc11);
            s = a1v[dd] + b4.z; acc12 = __fmaf_rn(s, __log2f(s), acc12);
            s = a1v[dd] + b4.w; acc13 = __fmaf_rn(s, __log2f(s), acc13);
        }
    }

    acc00 *= -0.5f; acc01 *= -0.5f; acc02 *= -0.5f; acc03 *= -0.5f;
    acc10 *= -0.5f; acc11 *= -0.5f; acc12 *= -0.5f; acc13 *= -0.5f;

    if (bz == SPLIT - 1) {
        // last-scheduled group folds the per-row constants; g_done >= EBLK
        // long before these blocks run, so the spin never iterates.
        if (tid == 0) {
            while (atomicAdd(&g_done, 0) < EBLK) __nanosleep(64);
        }
        __syncthreads();
        float ha0 = __ldcg(&g_hA[i0 + ty * 2]) + 1.0f;
        float ha1 = __ldcg(&g_hA[i0 + ty * 2 + 1]) + 1.0f;
        float hb0 = __ldcg(&g_hB[j0 + tx * 4]);
        float hb1 = __ldcg(&g_hB[j0 + tx * 4 + 1]);
        float hb2 = __ldcg(&g_hB[j0 + tx * 4 + 2]);
        float hb3 = __ldcg(&g_hB[j0 + tx * 4 + 3]);
        acc00 += ha0 + hb0; acc01 += ha0 + hb1;
        acc02 += ha0 + hb2; acc03 += ha0 + hb3;
        acc10 += ha1 + hb0; acc11 += ha1 + hb1;
        acc12 += ha1 + hb2; acc13 += ha1 + hb3;
    }

    // epilogue: RED.ADD.F32, spread addresses
    float* o0 = &out[(size_t)(i0 + ty * 2) * M + (j0 + tx * 4)];
    atomicAdd(o0 + 0, acc00);
    atomicAdd(o0 + 1, acc01);
    atomicAdd(o0 + 2, acc02);
    atomicAdd(o0 + 3, acc03);
    float* o1 = o0 + M;
    atomicAdd(o1 + 0, acc10);
    atomicAdd(o1 + 1, acc11);
    atomicAdd(o1 + 2, acc12);
    atomicAdd(o1 + 3, acc13);
}

extern "C" void kernel_launch(void* const* d_in, const int* in_sizes, int n_in,
                              void* d_out, int out_size) {
    const float* A = (const float*)d_in[0];
    const float* B = (const float*)d_in[1];
    float* out = (float*)d_out;
    const int N = in_sizes[0] / Dc;   // 1024
    const int M = in_sizes[1] / Dc;   // 1024

    cudaMemsetAsync(d_out, 0, (size_t)out_size * sizeof(float), 0);

    const int nblocks = EBLK + (M / TN) * (N / TM) * SPLIT;  // 64 + 8192
    jsd_fused<<<nblocks, 128>>>(A, B, out, M);
}